// round 1
// baseline (speedup 1.0000x reference)
#include <cuda_runtime.h>
#include <math.h>

// ---------------- problem dims ----------------
#define BB   8
#define TT   512
#define CC   2048
#define HH   32
#define ZZ   64
#define AA   2048            // H*Z
#define MR   (BB*TT)         // 4096 rows
#define TMX  32
#define TDX  64
#define EPS_GN (1e-5f * 64.0f)

// ---------------- scratch (__device__ globals; no cudaMalloc allowed) ----------------
__device__ float g_shift[BB*CC];
__device__ float g_reset[BB];
__device__ float g_xxx [MR*CC];
__device__ float g_mixt[MR*(5*TMX)];
__device__ float g_act [5u*MR*CC];     // f=0:td_in 1:kx 2:vx 3:rx 4:gx
__device__ float g_r   [MR*AA];
__device__ float g_k   [MR*AA];
__device__ float g_v   [MR*AA];
__device__ float g_gate[MR*AA];
__device__ float g_w   [MR*AA];        // -exp(raw)  (log-decay, pre-reset)
__device__ float g_td64[MR*TDX];
__device__ float g_xo  [MR*AA];
__device__ float g_gated[MR*AA];

// ---------------- prep: reset + shift ----------------
__global__ void prep_kernel(const int* __restrict__ positions,
                            const float* __restrict__ shift_state) {
    int i = blockIdx.x * blockDim.x + threadIdx.x;
    if (i >= BB*CC) return;
    int b = i / CC;
    float rst = (positions[b*TT] == 0) ? -100.0f : 0.0f;
    if ((i % CC) == 0) g_reset[b] = rst;
    g_shift[i] = shift_state[i] * expf(rst);
}

// ---------------- xxx = x + (shift - x)*maa_x ----------------
__global__ void mixx_kernel(const float* __restrict__ x,
                            const float* __restrict__ maa_x) {
    long i = (long)blockIdx.x * blockDim.x + threadIdx.x;
    long n = (long)MR*CC;
    if (i >= n) return;
    int c  = (int)(i % CC);
    int bt = (int)(i / CC);
    int b  = bt / TT;
    float xv = x[i];
    float sh = g_shift[b*CC + c];
    g_xxx[i] = xv + (sh - xv) * maa_x[c];
}

// ---------------- epilogues ----------------
// 0: plain   1: tanh   2: mix-act   3: -exp(td+acc)   4: silu
template<int EPI>
__device__ __forceinline__ float apply_epi(float acc, int row, int col,
                                           const float* p1, const float* p2,
                                           const float* p3) {
    if (EPI == 0) return acc;
    if (EPI == 1) return tanhf(acc);
    if (EPI == 2) {
        // p1 = maa_f [C], p2 = x [M,C], p3 = shift [B,C]
        float xv = p2[(long)row*CC + col];
        float sh = p3[(row/TT)*CC + col];
        return xv + (sh - xv) * (p1[col] + acc);
    }
    if (EPI == 3) return -expf(p1[col] + acc);
    // EPI == 4: silu
    return acc / (1.0f + expf(-acc));
}

// ---------------- generic guarded SGEMM: 64x64x16, TM=TN=4, 256 thr ----------------
template<int EPI>
__global__ void sgemm64(const float* __restrict__ A, const float* __restrict__ B,
                        float* __restrict__ Cmat, int M, int N, int K,
                        int lda, int ldb, int ldc,
                        const float* p1, const float* p2, const float* p3) {
    const int BM=64, BN=64, BK=16, TM=4, TN=4;
    __shared__ float As[BK*BM];   // [k][m]
    __shared__ float Bs[BK*BN];   // [k][n]
    int rowBase = blockIdx.y * BM;
    int colBase = blockIdx.x * BN;
    int tid = threadIdx.x;
    int aRow = tid & 63, aKb = (tid >> 6) * 4;
    int bK = tid >> 4, bN = (tid & 15) * 4;
    int trow = (tid / 16) * TM, tcol = (tid % 16) * TN;

    float acc[TM][TN];
    #pragma unroll
    for (int i=0;i<TM;i++)
        #pragma unroll
        for (int j=0;j<TN;j++) acc[i][j]=0.f;

    for (int k0 = 0; k0 < K; k0 += BK) {
        #pragma unroll
        for (int i=0;i<4;i++) {
            int kk = aKb + i;
            float va = 0.f;
            int gr = rowBase + aRow, gk = k0 + kk;
            if (gr < M && gk < K) va = A[(long)gr*lda + gk];
            As[kk*BM + aRow] = va;
        }
        #pragma unroll
        for (int j=0;j<4;j++) {
            float vb = 0.f;
            int gk = k0 + bK, gc = colBase + bN + j;
            if (gk < K && gc < N) vb = B[(long)gk*ldb + gc];
            Bs[bK*BN + bN + j] = vb;
        }
        __syncthreads();
        #pragma unroll
        for (int kk=0;kk<BK;kk++) {
            float rm[TM], rn[TN];
            #pragma unroll
            for (int i=0;i<TM;i++) rm[i] = As[kk*BM + trow + i];
            #pragma unroll
            for (int j=0;j<TN;j++) rn[j] = Bs[kk*BN + tcol + j];
            #pragma unroll
            for (int i=0;i<TM;i++)
                #pragma unroll
                for (int j=0;j<TN;j++) acc[i][j] = fmaf(rm[i], rn[j], acc[i][j]);
        }
        __syncthreads();
    }
    #pragma unroll
    for (int i=0;i<TM;i++) {
        int gr = rowBase + trow + i;
        if (gr >= M) continue;
        #pragma unroll
        for (int j=0;j<TN;j++) {
            int gc = colBase + tcol + j;
            if (gc >= N) continue;
            Cmat[(long)gr*ldc + gc] = apply_epi<EPI>(acc[i][j], gr, gc, p1, p2, p3);
        }
    }
}

// ---------------- fast SGEMM: 128x128x8, TM=TN=8, 256 thr (dims divisible) ----------------
template<int EPI>
__global__ void sgemm128(const float* __restrict__ A, const float* __restrict__ B,
                         float* __restrict__ Cmat, int M, int N, int K) {
    const int BM=128, BN=128, BK=8, TM=8, TN=8;
    __shared__ float As[BK*BM];   // transposed [k][m]
    __shared__ float Bs[BK*BN];   // [k][n]
    const float* Ag = A + (long)blockIdx.y * BM * K;
    const float* Bg = B + (long)blockIdx.x * BN;
    float* Cg = Cmat + (long)blockIdx.y * BM * N + (long)blockIdx.x * BN;
    int tid = threadIdx.x;
    int arow = tid >> 1, acol4 = (tid & 1) * 4;
    int brow = tid >> 5, bcol4 = (tid & 31) * 4;
    int trow = (tid / 16) * TM, tcol = (tid % 16) * TN;

    float acc[TM][TN];
    #pragma unroll
    for (int i=0;i<TM;i++)
        #pragma unroll
        for (int j=0;j<TN;j++) acc[i][j]=0.f;

    for (int k0 = 0; k0 < K; k0 += BK) {
        float4 a4 = *(const float4*)(Ag + (long)arow*K + acol4);
        As[(acol4+0)*BM + arow] = a4.x;
        As[(acol4+1)*BM + arow] = a4.y;
        As[(acol4+2)*BM + arow] = a4.z;
        As[(acol4+3)*BM + arow] = a4.w;
        *(float4*)(Bs + brow*BN + bcol4) = *(const float4*)(Bg + (long)brow*N + bcol4);
        __syncthreads();
        Ag += BK; Bg += (long)BK * N;
        #pragma unroll
        for (int kk=0;kk<BK;kk++) {
            float rm[TM], rn[TN];
            *(float4*)&rm[0] = *(const float4*)&As[kk*BM + trow];
            *(float4*)&rm[4] = *(const float4*)&As[kk*BM + trow + 4];
            *(float4*)&rn[0] = *(const float4*)&Bs[kk*BN + tcol];
            *(float4*)&rn[4] = *(const float4*)&Bs[kk*BN + tcol + 4];
            #pragma unroll
            for (int i=0;i<TM;i++)
                #pragma unroll
                for (int j=0;j<TN;j++) acc[i][j] = fmaf(rm[i], rn[j], acc[i][j]);
        }
        __syncthreads();
    }
    #pragma unroll
    for (int i=0;i<TM;i++) {
        #pragma unroll
        for (int j=0;j<TN;j+=4) {
            float4 o;
            o.x = apply_epi<EPI>(acc[i][j+0], 0,0, nullptr,nullptr,nullptr);
            o.y = apply_epi<EPI>(acc[i][j+1], 0,0, nullptr,nullptr,nullptr);
            o.z = apply_epi<EPI>(acc[i][j+2], 0,0, nullptr,nullptr,nullptr);
            o.w = apply_epi<EPI>(acc[i][j+3], 0,0, nullptr,nullptr,nullptr);
            *(float4*)(&Cg[(long)(trow+i)*N + tcol + j]) = o;
        }
    }
}

// ---------------- recurrence: one block per (b,h), 64 threads (v-columns) ----------------
__global__ void scan_kernel(const float* __restrict__ kv_state,
                            const float* __restrict__ faaaa) {
    int b = blockIdx.x / HH, h = blockIdx.x % HH;
    int v = threadIdx.x;                 // 0..63
    __shared__ float r_sh[ZZ], k_sh[ZZ], ew_sh[ZZ], part[2];

    float uv = faaaa[h*ZZ + v];
    float S[ZZ];
    const float* Sin = kv_state + ((long)(b*HH + h) * ZZ) * ZZ;
    #pragma unroll
    for (int kk=0;kk<ZZ;kk++) S[kk] = Sin[kk*ZZ + v];

    float reset_b = g_reset[b];
    int lane = v & 31, wrp = v >> 5;

    for (int t=0;t<TT;t++) {
        long base = (long)(b*TT + t) * AA + h*ZZ;
        float rv  = g_r[base + v];
        float kvv = g_k[base + v];
        float wl  = g_w[base + v];
        if (t == 0) wl += reset_b;
        float vv  = g_v[base + v];
        r_sh[v]  = rv;
        k_sh[v]  = kvv;
        ew_sh[v] = expf(wl);
        // ruk = sum_k r_k * u_k * k_k  (thread v contributes index k=v)
        float p = rv * uv * kvv;
        #pragma unroll
        for (int off=16; off; off >>= 1) p += __shfl_xor_sync(0xffffffffu, p, off);
        if (lane == 0) part[wrp] = p;
        __syncthreads();
        float ruk = part[0] + part[1];

        float o0 = 0.f, o1 = 0.f;
        #pragma unroll
        for (int kk=0;kk<ZZ;kk+=2) {
            o0 = fmaf(r_sh[kk],   S[kk],   o0);
            S[kk]   = fmaf(ew_sh[kk],   S[kk],   k_sh[kk]*vv);
            o1 = fmaf(r_sh[kk+1], S[kk+1], o1);
            S[kk+1] = fmaf(ew_sh[kk+1], S[kk+1], k_sh[kk+1]*vv);
        }
        g_xo[base + v] = o0 + o1 + ruk * vv;
        __syncthreads();
    }
}

// ---------------- groupnorm + gate: one warp per (bt, h) ----------------
__global__ void gn_gate_kernel(const float* __restrict__ ln_w,
                               const float* __restrict__ ln_b) {
    int gid = blockIdx.x * (blockDim.x >> 5) + (threadIdx.x >> 5);
    int lane = threadIdx.x & 31;
    if (gid >= MR*HH) return;
    int bt = gid / HH, h = gid % HH;
    long base = (long)bt*CC + h*ZZ;
    float x0 = g_xo[base + lane];
    float x1 = g_xo[base + lane + 32];
    float s = x0 + x1;
    #pragma unroll
    for (int off=16; off; off >>= 1) s += __shfl_xor_sync(0xffffffffu, s, off);
    float mu = s * (1.0f/64.0f);
    float d0 = x0 - mu, d1 = x1 - mu;
    float q = d0*d0 + d1*d1;
    #pragma unroll
    for (int off=16; off; off >>= 1) q += __shfl_xor_sync(0xffffffffu, q, off);
    float rs = rsqrtf(q * (1.0f/64.0f) + EPS_GN);
    int c0 = h*ZZ + lane, c1 = c0 + 32;
    float xn0 = d0 * rs * ln_w[c0] + ln_b[c0];
    float xn1 = d1 * rs * ln_w[c1] + ln_b[c1];
    g_gated[base + lane]      = xn0 * g_gate[base + lane];
    g_gated[base + lane + 32] = xn1 * g_gate[base + lane + 32];
}

// ---------------- launch ----------------
extern "C" void kernel_launch(void* const* d_in, const int* in_sizes, int n_in,
                              void* d_out, int out_size) {
    const float* x        = (const float*)d_in[0];
    const int*   pos      = (const int*)  d_in[1];
    const float* kv_state = (const float*)d_in[2];
    const float* shift_st = (const float*)d_in[3];
    const float* maa_x    = (const float*)d_in[4];
    const float* maa_f[5] = { (const float*)d_in[5], (const float*)d_in[6],
                              (const float*)d_in[7], (const float*)d_in[8],
                              (const float*)d_in[9] };          // w,k,v,r,g
    const float* w1       = (const float*)d_in[10];  // [C,160]
    const float* w2       = (const float*)d_in[11];  // [5,32,C]
    const float* tdecay   = (const float*)d_in[12];  // [A]
    const float* tdw1     = (const float*)d_in[13];  // [C,64]
    const float* tdw2     = (const float*)d_in[14];  // [64,A]
    const float* faaaa    = (const float*)d_in[15];  // [H,Z]
    const float* W_r      = (const float*)d_in[16];
    const float* W_k      = (const float*)d_in[17];
    const float* W_v      = (const float*)d_in[18];
    const float* W_g      = (const float*)d_in[19];
    const float* W_o      = (const float*)d_in[20];
    const float* ln_w     = (const float*)d_in[21];
    const float* ln_b     = (const float*)d_in[22];
    float* out = (float*)d_out;

    float *xxx, *mixt, *act, *rb, *kb, *vb, *gb, *wb, *td64, *gated;
    cudaGetSymbolAddress((void**)&xxx,  g_xxx);
    cudaGetSymbolAddress((void**)&mixt, g_mixt);
    cudaGetSymbolAddress((void**)&act,  g_act);
    cudaGetSymbolAddress((void**)&rb,   g_r);
    cudaGetSymbolAddress((void**)&kb,   g_k);
    cudaGetSymbolAddress((void**)&vb,   g_v);
    cudaGetSymbolAddress((void**)&gb,   g_gate);
    cudaGetSymbolAddress((void**)&wb,   g_w);
    cudaGetSymbolAddress((void**)&td64, g_td64);
    cudaGetSymbolAddress((void**)&gated,g_gated);

    const long MC = (long)MR * CC;

    // 1) reset + shift
    prep_kernel<<<(BB*CC + 255)/256, 256>>>(pos, shift_st);
    // 2) xxx
    mixx_kernel<<<(int)((MC + 255)/256), 256>>>(x, maa_x);
    // 3) mixt = tanh(xxx @ w1)   [4096,160]
    {
        dim3 grid((5*TMX + 63)/64, (MR + 63)/64);
        sgemm64<1><<<grid, 256>>>(xxx, w1, mixt, MR, 5*TMX, CC,
                                  CC, 5*TMX, 5*TMX, nullptr, nullptr, nullptr);
    }
    // 4) act_f = x + (shift-x)*(maa_f + mixt_f @ w2_f)   [K=32]
    {
        float* shp; cudaGetSymbolAddress((void**)&shp, g_shift);
        dim3 grid(CC/64, MR/64);
        for (int f=0; f<5; f++) {
            sgemm64<2><<<grid, 256>>>(mixt + f*TMX, w2 + (long)f*TMX*CC,
                                      act + (long)f*MC, MR, CC, TMX,
                                      5*TMX, CC, CC, maa_f[f], x, shp);
        }
    }
    // 5) big projections
    {
        dim3 grid(AA/128, MR/128);
        sgemm128<0><<<grid, 256>>>(act + 3*MC, W_r, rb, MR, AA, CC);
        sgemm128<0><<<grid, 256>>>(act + 1*MC, W_k, kb, MR, AA, CC);
        sgemm128<0><<<grid, 256>>>(act + 2*MC, W_v, vb, MR, AA, CC);
        sgemm128<4><<<grid, 256>>>(act + 4*MC, W_g, gb, MR, AA, CC);
    }
    // 6) td64 = tanh(td_in @ tdw1)   [4096,64]
    {
        dim3 grid(1, MR/64);
        sgemm64<1><<<grid, 256>>>(act, tdw1, td64, MR, TDX, CC,
                                  CC, TDX, TDX, nullptr, nullptr, nullptr);
    }
    // 7) w = -exp(time_decay + td64 @ tdw2)   [K=64]
    {
        dim3 grid(AA/64, MR/64);
        sgemm64<3><<<grid, 256>>>(td64, tdw2, wb, MR, AA, TDX,
                                  TDX, AA, AA, tdecay, nullptr, nullptr);
    }
    // 8) recurrence
    scan_kernel<<<BB*HH, ZZ>>>(kv_state, faaaa);
    // 9) groupnorm + gate
    gn_gate_kernel<<<(MR*HH + 7)/8, 256>>>(ln_w, ln_b);
    // 10) out = gated @ W_o
    {
        dim3 grid(CC/128, MR/128);
        sgemm128<0><<<grid, 256>>>(gated, W_o, out, MR, CC, AA);
    }
}

// round 3
// speedup vs baseline: 2.0229x; 2.0229x over previous
#include <cuda_runtime.h>
#include <cuda_bf16.h>
#include <math.h>
#include <stdint.h>

// ---------------- problem dims ----------------
#define BB   8
#define TT   512
#define CC   2048
#define HH   32
#define ZZ   64
#define AA   2048
#define MR   (BB*TT)         // 4096
#define TMX  32
#define TDX  64
#define NMIX 256             // padded 5*TMX=160 -> 256
#define NTD  128             // padded TDX=64 -> 128
#define EPS_GN (1e-5f * 64.0f)

// ---------------- scratch (__device__ globals) ----------------
__device__ float g_shift[BB*CC];
__device__ float g_reset[BB];
__device__ __align__(16) __nv_bfloat16 g_xxx_hi[MR*CC];
__device__ __align__(16) __nv_bfloat16 g_xxx_lo[MR*CC];
__device__ __align__(16) __nv_bfloat16 g_w1_hi[CC*NMIX];
__device__ __align__(16) __nv_bfloat16 g_w1_lo[CC*NMIX];
__device__ __align__(16) __nv_bfloat16 g_tdw1_hi[CC*NTD];
__device__ __align__(16) __nv_bfloat16 g_tdw1_lo[CC*NTD];
__device__ __align__(16) __nv_bfloat16 g_W_hi[5u*CC*AA];  // r,k,v,g,o
__device__ __align__(16) __nv_bfloat16 g_W_lo[5u*CC*AA];
__device__ float g_mixt[MR*NMIX];
__device__ __align__(16) __nv_bfloat16 g_act_hi[5u*MR*CC]; // f=0 td_in,1 kx,2 vx,3 rx,4 gx
__device__ __align__(16) __nv_bfloat16 g_act_lo[5u*MR*CC];
__device__ float g_r[MR*AA];
__device__ float g_k[MR*AA];
__device__ float g_v[MR*AA];
__device__ float g_gate[MR*AA];
__device__ float g_w[MR*AA];
__device__ float g_td64[MR*NTD];
__device__ float g_xo[MR*AA];
__device__ __align__(16) __nv_bfloat16 g_g_hi[MR*AA];
__device__ __align__(16) __nv_bfloat16 g_g_lo[MR*AA];

// ---------------- small helpers ----------------
__device__ __forceinline__ uint32_t smem_u32(const void* p) {
    return (uint32_t)__cvta_generic_to_shared(p);
}
__device__ __forceinline__ void split_write(float v, __nv_bfloat16* hi, __nv_bfloat16* lo, long i) {
    __nv_bfloat16 h = __float2bfloat16(v);
    hi[i] = h;
    lo[i] = __float2bfloat16(v - __bfloat162float(h));
}

// ---------------- prep: reset + shift ----------------
__global__ void prep_kernel(const int* __restrict__ positions,
                            const float* __restrict__ shift_state) {
    int i = blockIdx.x * blockDim.x + threadIdx.x;
    if (i >= BB*CC) return;
    int b = i / CC;
    float rst = (positions[b*TT] == 0) ? -100.0f : 0.0f;
    if ((i % CC) == 0) g_reset[b] = rst;
    g_shift[i] = shift_state[i] * expf(rst);
}

// ---------------- xxx = x + (shift-x)*maa_x, split to bf16 hi/lo ----------------
__global__ void mixx_kernel(const float* __restrict__ x,
                            const float* __restrict__ maa_x) {
    long i = (long)blockIdx.x * blockDim.x + threadIdx.x;
    if (i >= (long)MR*CC) return;
    int c  = (int)(i % CC);
    int b  = (int)(i / CC) / TT;
    float xv = x[i];
    float sh = g_shift[b*CC + c];
    float v = xv + (sh - xv) * maa_x[c];
    split_write(v, g_xxx_hi, g_xxx_lo, i);
}

// ---------------- pad + split fp32 -> bf16 hi/lo  [K,Nsrc] -> [K,Ndst] ----------------
__global__ void padsplit_kernel(const float* __restrict__ src,
                                __nv_bfloat16* __restrict__ hi,
                                __nv_bfloat16* __restrict__ lo,
                                int Nsrc, int Ndst, long total) {
    long i = (long)blockIdx.x * blockDim.x + threadIdx.x;
    if (i >= total) return;
    int  n = (int)(i % Ndst);
    long k = i / Ndst;
    float v = (n < Nsrc) ? src[k*Nsrc + n] : 0.0f;
    split_write(v, hi, lo, i);
}

// ---------------- tensor-core split-bf16 GEMM ----------------
// C[M,N] = Ahi*Bhi + Ahi*Blo + Alo*Bhi  (fp32 accum). 128x128x32 tile,
// 3-stage cp.async pipeline, warp tile 64x32 via mma.m16n8k16.
// EPI: 0 none, 1 tanh, 2 silu
template<int EPI>
__device__ __forceinline__ float hepi(float a) {
    if (EPI == 1) return tanhf(a);
    if (EPI == 2) return a / (1.0f + expf(-a));
    return a;
}

template<int EPI>
__global__ void __launch_bounds__(256)
hgemm_split(const __nv_bfloat16* __restrict__ Ahi, const __nv_bfloat16* __restrict__ Alo,
            const __nv_bfloat16* __restrict__ Bhi, const __nv_bfloat16* __restrict__ Blo,
            float* __restrict__ C, int M, int N, int K) {
    __shared__ __align__(16) unsigned char smem[3*16384]; // per stage: A 8KB + B 8KB
    const int tid  = threadIdx.x;
    const int lane = tid & 31, warp = tid >> 5;
    const int wm = warp >> 2, wn = warp & 3;       // 2 x 4 warp grid
    const int rowBase = blockIdx.y * 128, colBase = blockIdx.x * 128;
    const int kit = K >> 5;
    const int TOT = 3 * kit;
    const uint32_t sbase = smem_u32(smem);

    float acc[4][4][4];
    #pragma unroll
    for (int a=0;a<4;a++)
        #pragma unroll
        for (int b=0;b<4;b++)
            #pragma unroll
            for (int c=0;c<4;c++) acc[a][b][c]=0.f;

    auto load_stage = [&](int s, int kt) {
        const __nv_bfloat16* Ap = (kt < 2*kit) ? Ahi : Alo;
        const __nv_bfloat16* Bp = (kt >= kit && kt < 2*kit) ? Blo : Bhi;
        int koff = (kt % kit) << 5;
        uint32_t sA = sbase + s*16384;
        uint32_t sB = sA + 8192;
        #pragma unroll
        for (int i=0;i<2;i++) {
            int gid = tid*2 + i;
            int ar = gid >> 2, ac = gid & 3;                       // A: 128 rows x 4 chunks
            const void* asrc = Ap + (long)(rowBase+ar)*K + koff + ac*8;
            uint32_t adst = sA + ar*64 + ((ac ^ ((ar>>1)&3)) << 4);
            asm volatile("cp.async.cg.shared.global [%0], [%1], 16;\n" :: "r"(adst), "l"(asrc));
            int br = gid >> 4, bg = gid & 15;                      // B: 32 rows x 16 granules
            const void* bsrc = Bp + (long)(koff+br)*N + colBase + bg*8;
            uint32_t bdst = sB + br*256 + ((bg ^ (br&7)) << 4);
            asm volatile("cp.async.cg.shared.global [%0], [%1], 16;\n" :: "r"(bdst), "l"(bsrc));
        }
        asm volatile("cp.async.commit_group;\n" ::: "memory");
    };

    load_stage(0, 0);
    load_stage(1, 1);

    const int lr = lane & 15, lh = lane >> 4;
    for (int kt = 0; kt < TOT; kt++) {
        asm volatile("cp.async.wait_group 1;\n" ::: "memory");
        __syncthreads();
        int s = kt % 3;
        uint32_t sA = sbase + s*16384;
        uint32_t sB = sA + 8192;
        #pragma unroll
        for (int ks=0; ks<2; ks++) {
            uint32_t a[4][4], b[4][2];
            #pragma unroll
            for (int mi=0; mi<4; mi++) {
                int row = wm*64 + mi*16 + lr;
                int chunk = ks*2 + lh;
                uint32_t addr = sA + row*64 + ((chunk ^ ((row>>1)&3)) << 4);
                asm volatile("ldmatrix.sync.aligned.m8n8.x4.shared.b16 {%0,%1,%2,%3}, [%4];\n"
                    : "=r"(a[mi][0]),"=r"(a[mi][1]),"=r"(a[mi][2]),"=r"(a[mi][3]) : "r"(addr));
            }
            #pragma unroll
            for (int ni=0; ni<4; ni++) {
                int kr = ks*16 + lr;
                int gn = wn*4 + ni;
                uint32_t addr = sB + kr*256 + ((gn ^ (kr&7)) << 4);
                asm volatile("ldmatrix.sync.aligned.m8n8.x2.trans.shared.b16 {%0,%1}, [%2];\n"
                    : "=r"(b[ni][0]),"=r"(b[ni][1]) : "r"(addr));
            }
            #pragma unroll
            for (int mi=0; mi<4; mi++)
                #pragma unroll
                for (int ni=0; ni<4; ni++)
                    asm volatile("mma.sync.aligned.m16n8k16.row.col.f32.bf16.bf16.f32 "
                        "{%0,%1,%2,%3}, {%4,%5,%6,%7}, {%8,%9}, {%0,%1,%2,%3};\n"
                        : "+f"(acc[mi][ni][0]),"+f"(acc[mi][ni][1]),
                          "+f"(acc[mi][ni][2]),"+f"(acc[mi][ni][3])
                        : "r"(a[mi][0]),"r"(a[mi][1]),"r"(a[mi][2]),"r"(a[mi][3]),
                          "r"(b[ni][0]),"r"(b[ni][1]));
        }
        if (kt + 2 < TOT) load_stage((kt+2)%3, kt+2);
        else asm volatile("cp.async.commit_group;\n" ::: "memory");
    }

    // epilogue
    #pragma unroll
    for (int mi=0; mi<4; mi++) {
        int r0 = rowBase + wm*64 + mi*16 + (lane >> 2);
        #pragma unroll
        for (int ni=0; ni<4; ni++) {
            int c0 = colBase + wn*32 + ni*8 + (lane & 3)*2;
            float2 v0, v1;
            v0.x = hepi<EPI>(acc[mi][ni][0]); v0.y = hepi<EPI>(acc[mi][ni][1]);
            v1.x = hepi<EPI>(acc[mi][ni][2]); v1.y = hepi<EPI>(acc[mi][ni][3]);
            *(float2*)&C[(long)r0*N + c0]     = v0;
            *(float2*)&C[(long)(r0+8)*N + c0] = v1;
        }
    }
}

// ---------------- mix projection (K=32) + mix-activation + bf16 split ----------------
// out = x + (shift-x)*(maa_f + mixt[:,foff:foff+32] @ w2_f), written as hi/lo bf16
__global__ void __launch_bounds__(256)
mix_gemm_split(const float* __restrict__ Amixt,      // [MR, NMIX]
               const float* __restrict__ Bw2,        // [32, CC]
               const float* __restrict__ maa_f,      // [CC]
               const float* __restrict__ x,          // [MR, CC]
               __nv_bfloat16* __restrict__ outhi,
               __nv_bfloat16* __restrict__ outlo,
               int foff) {
    __shared__ float As[32*64];   // [k][m]
    __shared__ float Bs[32*64];   // [k][n]
    int rowBase = blockIdx.y * 64, colBase = blockIdx.x * 64;
    int tid = threadIdx.x;
    for (int i = tid; i < 64*32; i += 256) {
        int m = i & 63, k = i >> 6;
        As[k*64 + m] = Amixt[(long)(rowBase+m)*NMIX + foff + k];
    }
    for (int i = tid; i < 32*64; i += 256) {
        int n = i & 63, k = i >> 6;
        Bs[k*64 + n] = Bw2[(long)k*CC + colBase + n];
    }
    __syncthreads();
    int trow = (tid/16)*4, tcol = (tid%16)*4;
    float acc[4][4];
    #pragma unroll
    for (int i=0;i<4;i++)
        #pragma unroll
        for (int j=0;j<4;j++) acc[i][j]=0.f;
    #pragma unroll
    for (int kk=0; kk<32; kk++) {
        float rm[4], rn[4];
        #pragma unroll
        for (int i=0;i<4;i++) rm[i] = As[kk*64 + trow + i];
        #pragma unroll
        for (int j=0;j<4;j++) rn[j] = Bs[kk*64 + tcol + j];
        #pragma unroll
        for (int i=0;i<4;i++)
            #pragma unroll
            for (int j=0;j<4;j++) acc[i][j] = fmaf(rm[i], rn[j], acc[i][j]);
    }
    #pragma unroll
    for (int i=0;i<4;i++) {
        int gr = rowBase + trow + i;
        int bb = gr / TT;
        #pragma unroll
        for (int j=0;j<4;j++) {
            int gc = colBase + tcol + j;
            float xv = x[(long)gr*CC + gc];
            float sh = g_shift[bb*CC + gc];
            float v = xv + (sh - xv) * (maa_f[gc] + acc[i][j]);
            split_write(v, outhi, outlo, (long)gr*CC + gc);
        }
    }
}

// ---------------- fp32 SGEMM 64x64 for the K=64 decay GEMM ----------------
// epilogue: out = -exp(p1[col] + acc)
__global__ void sgemm64_decay(const float* __restrict__ A, const float* __restrict__ B,
                              float* __restrict__ Cmat, int M, int N, int K,
                              int lda, int ldb, int ldc, const float* __restrict__ p1) {
    const int BM=64, BN=64, BK=16;
    __shared__ float As[BK*BM];
    __shared__ float Bs[BK*BN];
    int rowBase = blockIdx.y * BM, colBase = blockIdx.x * BN;
    int tid = threadIdx.x;
    int aRow = tid & 63, aKb = (tid >> 6) * 4;
    int bK = tid >> 4, bN = (tid & 15) * 4;
    int trow = (tid/16)*4, tcol = (tid%16)*4;
    float acc[4][4];
    #pragma unroll
    for (int i=0;i<4;i++)
        #pragma unroll
        for (int j=0;j<4;j++) acc[i][j]=0.f;
    for (int k0 = 0; k0 < K; k0 += BK) {
        #pragma unroll
        for (int i=0;i<4;i++) {
            int kk = aKb + i;
            As[kk*BM + aRow] = A[(long)(rowBase+aRow)*lda + k0 + kk];
        }
        #pragma unroll
        for (int j=0;j<4;j++)
            Bs[bK*BN + bN + j] = B[(long)(k0+bK)*ldb + colBase + bN + j];
        __syncthreads();
        #pragma unroll
        for (int kk=0;kk<BK;kk++) {
            float rm[4], rn[4];
            #pragma unroll
            for (int i=0;i<4;i++) rm[i] = As[kk*BM + trow + i];
            #pragma unroll
            for (int j=0;j<4;j++) rn[j] = Bs[kk*BN + tcol + j];
            #pragma unroll
            for (int i=0;i<4;i++)
                #pragma unroll
                for (int j=0;j<4;j++) acc[i][j] = fmaf(rm[i], rn[j], acc[i][j]);
        }
        __syncthreads();
    }
    #pragma unroll
    for (int i=0;i<4;i++) {
        int gr = rowBase + trow + i;
        #pragma unroll
        for (int j=0;j<4;j++) {
            int gc = colBase + tcol + j;
            Cmat[(long)gr*ldc + gc] = -expf(p1[gc] + acc[i][j]);
        }
    }
}

// ---------------- recurrence: one block per (b,h), 64 threads ----------------
__global__ void scan_kernel(const float* __restrict__ kv_state,
                            const float* __restrict__ faaaa) {
    int b = blockIdx.x / HH, h = blockIdx.x % HH;
    int v = threadIdx.x;
    __shared__ float r_sh[ZZ], k_sh[ZZ], ew_sh[ZZ], part[2];

    float uv = faaaa[h*ZZ + v];
    float S[ZZ];
    const float* Sin = kv_state + ((long)(b*HH + h) * ZZ) * ZZ;
    #pragma unroll
    for (int kk=0;kk<ZZ;kk++) S[kk] = Sin[kk*ZZ + v];

    float reset_b = g_reset[b];
    int lane = v & 31, wrp = v >> 5;

    for (int t=0;t<TT;t++) {
        long base = (long)(b*TT + t) * AA + h*ZZ;
        float rv  = g_r[base + v];
        float kvv = g_k[base + v];
        float wl  = g_w[base + v];
        if (t == 0) wl += reset_b;
        float vv  = g_v[base + v];
        r_sh[v]  = rv;
        k_sh[v]  = kvv;
        ew_sh[v] = expf(wl);
        float p = rv * uv * kvv;
        #pragma unroll
        for (int off=16; off; off >>= 1) p += __shfl_xor_sync(0xffffffffu, p, off);
        if (lane == 0) part[wrp] = p;
        __syncthreads();
        float ruk = part[0] + part[1];

        float o0 = 0.f, o1 = 0.f;
        #pragma unroll
        for (int kk=0;kk<ZZ;kk+=2) {
            o0 = fmaf(r_sh[kk],   S[kk],   o0);
            S[kk]   = fmaf(ew_sh[kk],   S[kk],   k_sh[kk]*vv);
            o1 = fmaf(r_sh[kk+1], S[kk+1], o1);
            S[kk+1] = fmaf(ew_sh[kk+1], S[kk+1], k_sh[kk+1]*vv);
        }
        g_xo[base + v] = o0 + o1 + ruk * vv;
        __syncthreads();
    }
}

// ---------------- groupnorm + gate, writes gated as bf16 hi/lo ----------------
__global__ void gn_gate_kernel(const float* __restrict__ ln_w,
                               const float* __restrict__ ln_b) {
    int gid = blockIdx.x * (blockDim.x >> 5) + (threadIdx.x >> 5);
    int lane = threadIdx.x & 31;
    if (gid >= MR*HH) return;
    int bt = gid / HH, h = gid % HH;
    long base = (long)bt*CC + h*ZZ;
    float x0 = g_xo[base + lane];
    float x1 = g_xo[base + lane + 32];
    float s = x0 + x1;
    #pragma unroll
    for (int off=16; off; off >>= 1) s += __shfl_xor_sync(0xffffffffu, s, off);
    float mu = s * (1.0f/64.0f);
    float d0 = x0 - mu, d1 = x1 - mu;
    float q = d0*d0 + d1*d1;
    #pragma unroll
    for (int off=16; off; off >>= 1) q += __shfl_xor_sync(0xffffffffu, q, off);
    float rs = rsqrtf(q * (1.0f/64.0f) + EPS_GN);
    int c0 = h*ZZ + lane, c1 = c0 + 32;
    float g0 = (d0 * rs * ln_w[c0] + ln_b[c0]) * g_gate[base + lane];
    float g1 = (d1 * rs * ln_w[c1] + ln_b[c1]) * g_gate[base + lane + 32];
    split_write(g0, g_g_hi, g_g_lo, base + lane);
    split_write(g1, g_g_hi, g_g_lo, base + lane + 32);
}

// ---------------- launch ----------------
extern "C" void kernel_launch(void* const* d_in, const int* in_sizes, int n_in,
                              void* d_out, int out_size) {
    const float* x        = (const float*)d_in[0];
    const int*   pos      = (const int*)  d_in[1];
    const float* kv_state = (const float*)d_in[2];
    const float* shift_st = (const float*)d_in[3];
    const float* maa_x    = (const float*)d_in[4];
    const float* maa_f[5] = { (const float*)d_in[5], (const float*)d_in[6],
                              (const float*)d_in[7], (const float*)d_in[8],
                              (const float*)d_in[9] };       // w,k,v,r,g
    const float* w1       = (const float*)d_in[10];   // [C,160]
    const float* w2       = (const float*)d_in[11];   // [5,32,C]
    const float* tdecay   = (const float*)d_in[12];   // [A]
    const float* tdw1     = (const float*)d_in[13];   // [C,64]
    const float* tdw2     = (const float*)d_in[14];   // [64,A]
    const float* faaaa    = (const float*)d_in[15];   // [H,Z]
    const float* Wmat[5]  = { (const float*)d_in[16], (const float*)d_in[17],
                              (const float*)d_in[18], (const float*)d_in[19],
                              (const float*)d_in[20] };      // W_r,W_k,W_v,W_g,W_o
    const float* ln_w     = (const float*)d_in[21];
    const float* ln_b     = (const float*)d_in[22];
    float* out = (float*)d_out;

    float *mixt, *rb, *kb, *vb, *gateb, *wb, *td64;
    __nv_bfloat16 *xxh, *xxl, *w1h, *w1l, *tdh, *tdl, *Wh, *Wl, *ah, *al, *gh, *gl;
    cudaGetSymbolAddress((void**)&mixt, g_mixt);
    cudaGetSymbolAddress((void**)&rb,   g_r);
    cudaGetSymbolAddress((void**)&kb,   g_k);
    cudaGetSymbolAddress((void**)&vb,   g_v);
    cudaGetSymbolAddress((void**)&gateb,g_gate);
    cudaGetSymbolAddress((void**)&wb,   g_w);
    cudaGetSymbolAddress((void**)&td64, g_td64);
    cudaGetSymbolAddress((void**)&xxh,  g_xxx_hi);
    cudaGetSymbolAddress((void**)&xxl,  g_xxx_lo);
    cudaGetSymbolAddress((void**)&w1h,  g_w1_hi);
    cudaGetSymbolAddress((void**)&w1l,  g_w1_lo);
    cudaGetSymbolAddress((void**)&tdh,  g_tdw1_hi);
    cudaGetSymbolAddress((void**)&tdl,  g_tdw1_lo);
    cudaGetSymbolAddress((void**)&Wh,   g_W_hi);
    cudaGetSymbolAddress((void**)&Wl,   g_W_lo);
    cudaGetSymbolAddress((void**)&ah,   g_act_hi);
    cudaGetSymbolAddress((void**)&al,   g_act_lo);
    cudaGetSymbolAddress((void**)&gh,   g_g_hi);
    cudaGetSymbolAddress((void**)&gl,   g_g_lo);

    const long MC = (long)MR * CC;
    const long WC = (long)CC * AA;

    // 1) reset + shift
    prep_kernel<<<(BB*CC + 255)/256, 256>>>(pos, shift_st);
    // 2) xxx (split bf16)
    mixx_kernel<<<(int)((MC + 255)/256), 256>>>(x, maa_x);
    // 3) weight splits
    padsplit_kernel<<<(int)(((long)CC*NMIX + 255)/256), 256>>>(w1, w1h, w1l, 5*TMX, NMIX, (long)CC*NMIX);
    padsplit_kernel<<<(int)(((long)CC*NTD + 255)/256), 256>>>(tdw1, tdh, tdl, TDX, NTD, (long)CC*NTD);
    for (int i = 0; i < 5; i++)
        padsplit_kernel<<<(int)((WC + 255)/256), 256>>>(Wmat[i], Wh + i*WC, Wl + i*WC, AA, AA, WC);
    // 4) mixt = tanh(xxx @ w1pad)   [4096, 256]
    hgemm_split<1><<<dim3(NMIX/128, MR/128), 256>>>(xxh, xxl, w1h, w1l, mixt, MR, NMIX, CC);
    // 5) act_f (mix activation, split bf16)  x5
    {
        dim3 grid(CC/64, MR/64);
        for (int f = 0; f < 5; f++)
            mix_gemm_split<<<grid, 256>>>(mixt, w2 + (long)f*TMX*CC, maa_f[f], x,
                                          ah + (long)f*MC, al + (long)f*MC, f*TMX);
    }
    // 6) big projections (tensor cores)
    {
        dim3 grid(AA/128, MR/128);
        hgemm_split<0><<<grid, 256>>>(ah + 3*MC, al + 3*MC, Wh + 0*WC, Wl + 0*WC, rb,    MR, AA, CC);
        hgemm_split<0><<<grid, 256>>>(ah + 1*MC, al + 1*MC, Wh + 1*WC, Wl + 1*WC, kb,    MR, AA, CC);
        hgemm_split<0><<<grid, 256>>>(ah + 2*MC, al + 2*MC, Wh + 2*WC, Wl + 2*WC, vb,    MR, AA, CC);
        hgemm_split<2><<<grid, 256>>>(ah + 4*MC, al + 4*MC, Wh + 3*WC, Wl + 3*WC, gateb, MR, AA, CC);
    }
    // 7) td64 = tanh(td_in @ tdw1pad)  [4096, 128]
    hgemm_split<1><<<dim3(NTD/128, MR/128), 256>>>(ah, al, tdh, tdl, td64, MR, NTD, CC);
    // 8) w = -exp(time_decay + td64 @ tdw2)   (K=64)
    sgemm64_decay<<<dim3(AA/64, MR/64), 256>>>(td64, tdw2, wb, MR, AA, TDX, NTD, AA, AA, tdecay);
    // 9) recurrence
    scan_kernel<<<BB*HH, ZZ>>>(kv_state, faaaa);
    // 10) groupnorm + gate (split bf16)
    gn_gate_kernel<<<(MR*HH + 7)/8, 256>>>(ln_w, ln_b);
    // 11) out = gated @ W_o
    hgemm_split<0><<<dim3(CC/128, MR/128), 256>>>(gh, gl, Wh + 4*WC, Wl + 4*WC, out, MR, CC, AA);
}